// round 1
// baseline (speedup 1.0000x reference)
#include <cuda_runtime.h>
#include <cstdint>

#define N_NEURONS 8192
#define M_DIM (N_NEURONS + 1)          // 8193
#define EPS_ALPHA 1e-5f

// Output layout (fp32):
//   [0, N)                      cl
//   [N, 2N)                     cu
//   [2N, 2N + M*M)              A_l  (row-major M x M)
//   [2N + M*M, 2N + 2*M*M)      A_u
__global__ void relu6_relax_fill(const float* __restrict__ lower,
                                 const float* __restrict__ upper,
                                 float* __restrict__ out)
{
    int i = blockIdx.x * blockDim.x + threadIdx.x;
    if (i >= N_NEURONS) return;

    const long long MM = (long long)M_DIM * (long long)M_DIM;
    float* cl_out = out;
    float* cu_out = out + N_NEURONS;
    float* A_l    = out + 2 * N_NEURONS;
    float* A_u    = A_l + MM;

    float l = lower[i];
    float u = upper[i];

    // guarded denominators (match reference exactly)
    float den_ul = (u > l)    ? (u - l)    : 1.0f;
    float den_6l = (l < 6.0f) ? (6.0f - l) : 1.0f;
    float u_safe = (u > 0.0f) ? u          : 1.0f;

    bool mA = (u > 0.0f) && (u <= 6.0f) && (l >= 0.0f);
    bool mB = (u > 0.0f) && (u <= 6.0f) && (l <  0.0f);
    bool mC = (u > 6.0f) && (l <= 0.0f);
    bool mD = (u > 6.0f) && (l >  0.0f) && (l <= 6.0f);
    bool mE = (l > 6.0f);

    float alpha_B = (u < -l) ? EPS_ALPHA : 1.0f;
    float lam_B   = u / den_ul;
    float aU_C    = ((u - 6.0f) < (6.0f - l)) ? (6.0f / den_6l) : EPS_ALPHA;
    float aL_C    = (u < -l) ? EPS_ALPHA : (6.0f / u_safe);
    float aU_D    = ((u - 6.0f) < (6.0f - l)) ? 1.0f : EPS_ALPHA;
    float aL_D    = (6.0f - l) / den_ul;

    float fA = mA ? 1.0f : 0.0f;
    float fB = mB ? 1.0f : 0.0f;
    float fC = mC ? 1.0f : 0.0f;
    float fD = mD ? 1.0f : 0.0f;
    float fE = mE ? 1.0f : 0.0f;

    float diag_u = fA * 1.0f + fB * lam_B   + fC * aU_C + fD * aU_D;
    float diag_l = fA * 1.0f + fB * alpha_B + fC * aL_C + fD * aL_D;
    float bias_u = fB * (-lam_B * l)
                 + fC * (6.0f * (1.0f - aU_C))
                 + fD * (6.0f * (1.0f - aU_D))
                 + fE * 6.0f;
    float bias_l = fD * (l * (1.0f - aL_D)) + fE * 6.0f;
    float cu_v   = fA * u + fB * u
                 + fC * (6.0f + aU_C * (u - 6.0f))
                 + fD * (6.0f + aU_D * (u - 6.0f))
                 + fE * 6.0f;
    float cl_v   = fA * l + fB * (alpha_B * l) + fC * (aL_C * l)
                 + fD * l + fE * 6.0f;

    cl_out[i] = cl_v;
    cu_out[i] = cu_v;

    // diagonal entries
    long long dpos = (long long)i * M_DIM + i;
    A_l[dpos] = diag_l;
    A_u[dpos] = diag_u;

    // bias row (last row, columns 0..N-1)
    long long brow = (long long)(M_DIM - 1) * M_DIM;
    A_l[brow + i] = bias_l;
    A_u[brow + i] = bias_u;

    // corner [-1,-1] = 1.0 (one thread)
    if (i == 0) {
        A_l[brow + (M_DIM - 1)] = 1.0f;
        A_u[brow + (M_DIM - 1)] = 1.0f;
    }
}

extern "C" void kernel_launch(void* const* d_in, const int* in_sizes, int n_in,
                              void* d_out, int out_size)
{
    const float* lower = (const float*)d_in[0];
    const float* upper = (const float*)d_in[1];
    float* out = (float*)d_out;

    // Zero the entire output (cl/cu regions get overwritten anyway; the two
    // matrices are all-zero except diag + bias row + corner).
    size_t bytes = (size_t)out_size * sizeof(float);
    cudaMemsetAsync(d_out, 0, bytes, 0);

    int threads = 256;
    int blocks = (N_NEURONS + threads - 1) / threads;
    relu6_relax_fill<<<blocks, threads>>>(lower, upper, out);
}

// round 2
// speedup vs baseline: 1.0620x; 1.0620x over previous
#include <cuda_runtime.h>
#include <cstdint>

#define NN 8192u
#define MD 8193u
#define MM 67125249u          // 8193*8193
#define BIAS_START 67117056u  // 8192*8193 (start of last row within a matrix)
#define DIAG_STRIDE 8194u     // diag element i lives at i*(MD+1)
#define CLCU 16384u           // 2*NN floats of cl/cu before the matrices
#define EPS_ALPHA 1e-5f

struct Relax {
    float cl, cu, dl, du, bl, bu;
};

__device__ __forceinline__ Relax relax(float l, float u)
{
    float den_ul = (u > l)    ? (u - l)    : 1.0f;
    float den_6l = (l < 6.0f) ? (6.0f - l) : 1.0f;
    float u_safe = (u > 0.0f) ? u          : 1.0f;

    bool mA = (u > 0.0f) && (u <= 6.0f) && (l >= 0.0f);
    bool mB = (u > 0.0f) && (u <= 6.0f) && (l <  0.0f);
    bool mC = (u > 6.0f) && (l <= 0.0f);
    bool mD = (u > 6.0f) && (l >  0.0f) && (l <= 6.0f);
    bool mE = (l > 6.0f);

    float alpha_B = (u < -l) ? EPS_ALPHA : 1.0f;
    float lam_B   = u / den_ul;
    float aU_C    = ((u - 6.0f) < (6.0f - l)) ? (6.0f / den_6l) : EPS_ALPHA;
    float aL_C    = (u < -l) ? EPS_ALPHA : (6.0f / u_safe);
    float aU_D    = ((u - 6.0f) < (6.0f - l)) ? 1.0f : EPS_ALPHA;
    float aL_D    = (6.0f - l) / den_ul;

    float fA = mA ? 1.0f : 0.0f;
    float fB = mB ? 1.0f : 0.0f;
    float fC = mC ? 1.0f : 0.0f;
    float fD = mD ? 1.0f : 0.0f;
    float fE = mE ? 1.0f : 0.0f;

    Relax r;
    r.du = fA * 1.0f + fB * lam_B   + fC * aU_C + fD * aU_D;
    r.dl = fA * 1.0f + fB * alpha_B + fC * aL_C + fD * aL_D;
    r.bu = fB * (-lam_B * l)
         + fC * (6.0f * (1.0f - aU_C))
         + fD * (6.0f * (1.0f - aU_D))
         + fE * 6.0f;
    r.bl = fD * (l * (1.0f - aL_D)) + fE * 6.0f;
    r.cu = fA * u + fB * u
         + fC * (6.0f + aU_C * (u - 6.0f))
         + fD * (6.0f + aU_D * (u - 6.0f))
         + fE * 6.0f;
    r.cl = fA * l + fB * (alpha_B * l) + fC * (aL_C * l)
         + fD * l + fE * 6.0f;
    return r;
}

// Value of one in-matrix element at offset p (0 <= p < MM) for matrix L (isL) or U.
__device__ __forceinline__ float mat_value(unsigned p, bool isL,
                                           const float* __restrict__ lower,
                                           const float* __restrict__ upper)
{
    if (p >= BIAS_START) {
        unsigned col = p - BIAS_START;
        if (col == NN) return 1.0f;          // [-1,-1] corner
        // bias row, col in [0, NN)
        Relax r = relax(lower[col], upper[col]);
        return isL ? r.bl : r.bu;
    }
    unsigned row = p / DIAG_STRIDE;          // umulhi-based constant divide
    if (p == row * DIAG_STRIDE) {            // diagonal element [row][row]
        Relax r = relax(lower[row], upper[row]);
        return isL ? r.dl : r.du;
    }
    return 0.0f;
}

// Value of one element of the full concatenated output at global float offset oe.
__device__ __forceinline__ float out_value(unsigned oe,
                                           const float* __restrict__ lower,
                                           const float* __restrict__ upper)
{
    if (oe < CLCU) {
        unsigned i = oe & (NN - 1u);
        Relax r = relax(lower[i], upper[i]);
        return (oe < NN) ? r.cl : r.cu;
    }
    unsigned r = oe - CLCU;
    if (r < MM) return mat_value(r, true, lower, upper);
    return mat_value(r - MM, false, lower, upper);
}

__global__ void relu6_fused(const float* __restrict__ lower,
                            const float* __restrict__ upper,
                            float* __restrict__ out,
                            unsigned out_size)
{
    unsigned idx = blockIdx.x * blockDim.x + threadIdx.x;
    unsigned o = idx * 4u;
    if (o >= out_size) return;

    if (o + 4u <= out_size) {
        // Fast pure-zero test for chunks fully inside one matrix.
        if (o >= CLCU) {
            unsigned r = o - CLCU;
            bool pureL = (r + 4u <= MM);
            bool pureU = (r >= MM);
            if (pureL | pureU) {
                unsigned p = pureL ? r : (r - MM);
                bool bias = (p + 3u >= BIAS_START);
                unsigned q = (p + 3u) / DIAG_STRIDE;
                bool diag = (q * DIAG_STRIDE >= p);  // multiple of 8194 in [p, p+4)
                if (!(bias | diag)) {
                    float4 z = make_float4(0.f, 0.f, 0.f, 0.f);
                    *reinterpret_cast<float4*>(out + o) = z;
                    return;
                }
            }
        }
        // Slow per-element path (cl/cu region, diag/bias chunks, boundary straddle).
        float4 v;
        v.x = out_value(o + 0u, lower, upper);
        v.y = out_value(o + 1u, lower, upper);
        v.z = out_value(o + 2u, lower, upper);
        v.w = out_value(o + 3u, lower, upper);
        *reinterpret_cast<float4*>(out + o) = v;
        return;
    }

    // Tail (out_size % 4 == 2): per-element.
    for (unsigned e = o; e < out_size; ++e)
        out[e] = out_value(e, lower, upper);
}

extern "C" void kernel_launch(void* const* d_in, const int* in_sizes, int n_in,
                              void* d_out, int out_size)
{
    const float* lower = (const float*)d_in[0];
    const float* upper = (const float*)d_in[1];
    float* out = (float*)d_out;

    unsigned n = (unsigned)out_size;
    unsigned nchunks = (n + 3u) / 4u;
    unsigned threads = 256u;
    unsigned blocks = (nchunks + threads - 1u) / threads;
    relu6_fused<<<blocks, threads>>>(lower, upper, out, n);
}